// round 13
// baseline (speedup 1.0000x reference)
#include <cuda_runtime.h>
#include <math.h>

#define B  8
#define TQ 128
#define TK 512
#define DD 256
#define HH 256

// Scratch (no allocations allowed)
__device__ float g_qp[B * TQ * HH];     // 1 MB
__device__ float g_kp[B * TK * HH];     // 4 MB (rows >= valid_lens[b] stay garbage — masked later)
__device__ float g_attn[B * TQ * TK];   // 2 MB (raw scores; masked cols garbage — masked later)

typedef unsigned long long u64;

__device__ __forceinline__ float tanh_fast(float x) {
    float y;
    asm("tanh.approx.f32 %0, %1;" : "=f"(y) : "f"(x));
    return y;
}
__device__ __forceinline__ u64 ffma2(u64 a, u64 b, u64 c) {
    u64 d;
    asm("fma.rn.f32x2 %0, %1, %2, %3;" : "=l"(d) : "l"(a), "l"(b), "l"(c));
    return d;
}
__device__ __forceinline__ u64 fadd2(u64 a, u64 b) {
    u64 d;
    asm("add.rn.f32x2 %0, %1, %2;" : "=l"(d) : "l"(a), "l"(b));
    return d;
}
__device__ __forceinline__ u64 pack2(float lo, float hi) {
    u64 r;
    asm("mov.b64 %0, {%1, %2};" : "=l"(r) : "f"(lo), "f"(hi));
    return r;
}
__device__ __forceinline__ float2 unpack2(u64 v) {
    float lo, hi;
    asm("mov.b64 {%0, %1}, %2;" : "=f"(lo), "=f"(hi) : "l"(v));
    return make_float2(lo, hi);
}
__device__ __forceinline__ float sum2(u64 v) {
    float2 f = unpack2(v);
    return f.x + f.y;
}

__device__ __forceinline__ unsigned smem_u32(const void* p) {
    return (unsigned)__cvta_generic_to_shared(p);
}
__device__ __forceinline__ void cp_async16(unsigned dst, const void* src) {
    asm volatile("cp.async.cg.shared.global [%0], [%1], 16;\n"
                 :: "r"(dst), "l"(src));
}
__device__ __forceinline__ void cp_commit() {
    asm volatile("cp.async.commit_group;\n");
}
template <int N>
__device__ __forceinline__ void cp_wait() {
    asm volatile("cp.async.wait_group %0;\n" :: "n"(N));
}

// D = A(16x8, row) * B(8x8, col) + D, tf32 in / f32 accum.
// Operands are raw f32 bits: HW reads the top 19 bits (RZ truncation to tf32),
// saving all cvt.rna.tf32 instructions at ~2^-10 operand error.
__device__ __forceinline__ void mma_tf32(float* c, const unsigned* a, const unsigned* b) {
    asm("mma.sync.aligned.m16n8k8.row.col.f32.tf32.tf32.f32 "
        "{%0,%1,%2,%3}, {%4,%5,%6,%7}, {%8,%9}, {%0,%1,%2,%3};"
        : "+f"(c[0]), "+f"(c[1]), "+f"(c[2]), "+f"(c[3])
        : "r"(a[0]), "r"(a[1]), "r"(a[2]), "r"(a[3]), "r"(b[0]), "r"(b[1]));
}

// ---------------------------------------------------------------------------
// Combined projection GEMM on tensor cores (TF32 mma.sync, no-cvt fast path).
// 64x64 block tile, 256 threads (8 warps: 2m x 4n, warp tile 32m x 16n).
// BK=32, cp.async THREE-stage circular buffer: 2 load groups in flight.
// Masked 64-row k blocks exit early.
// ---------------------------------------------------------------------------
__global__ __launch_bounds__(256) void proj_kernel(
    const float* __restrict__ q, const float* __restrict__ k,
    const float* __restrict__ Wq, const float* __restrict__ Wk,
    const int* __restrict__ valid_lens) {
    __shared__ float As[3][64][36];   // [stage][m][k]
    __shared__ float Ws[3][32][72];   // [stage][k][n]

    const int by = blockIdx.y;
    const float* A; const float* W; float* C; int bm;
    if (by < 16) {
        A = q; W = Wq; C = g_qp; bm = by * 64;
    } else {
        bm = (by - 16) * 64;             // k row in [0, 4096)
        int b = bm >> 9;
        int local = bm & 511;
        if (local >= valid_lens[b]) return;   // fully-masked k rows
        A = k; W = Wk; C = g_kp;
    }

    const int t    = threadIdx.x;
    const int bn   = blockIdx.x * 64;
    const int lane = t & 31;
    const int wid  = t >> 5;
    const int m0   = (wid & 1) * 32;
    const int n0   = (wid >> 1) * 16;
    const int ln4  = lane >> 2;          // 0..7
    const int lm4  = lane & 3;           // 0..3

    const float* Abase = A + (size_t)bm * 256;
    const float* Wbase = W + bn;

    unsigned sA[3], sB[3];
    #pragma unroll
    for (int s = 0; s < 3; s++) {
        sA[s] = smem_u32(&As[s][0][0]);
        sB[s] = smem_u32(&Ws[s][0][0]);
    }

    #define LOAD_STAGE(stg, kt)                                                   \
        do {                                                                      \
            int _k0 = (kt) * 32;                                                  \
            _Pragma("unroll")                                                     \
            for (int j = 0; j < 2; j++) {                                         \
                int u = t + 256 * j;                                              \
                int r = u >> 3, c4 = (u & 7) * 4;                                 \
                cp_async16(sA[stg] + (r * 36 + c4) * 4,                           \
                           Abase + (size_t)r * 256 + _k0 + c4);                   \
            }                                                                     \
            _Pragma("unroll")                                                     \
            for (int j = 0; j < 2; j++) {                                         \
                int u = t + 256 * j;                                              \
                int r = u >> 4, c4 = (u & 15) * 4;                                \
                cp_async16(sB[stg] + (r * 72 + c4) * 4,                           \
                           Wbase + (size_t)(_k0 + r) * 256 + c4);                 \
            }                                                                     \
            cp_commit();                                                          \
        } while (0)

    float acc[2][2][4] = {};   // [mi][ni][4]

    LOAD_STAGE(0, 0);
    LOAD_STAGE(1, 1);

    #pragma unroll 1
    for (int kt = 0; kt < 8; kt++) {
        const int stg = kt % 3;
        if (kt + 2 < 8) {
            LOAD_STAGE((kt + 2) % 3, kt + 2);   // keep 2 groups in flight
            cp_wait<2>();                       // oldest (stage kt) complete
        } else {
            cp_wait<0>();
        }
        __syncthreads();

        #pragma unroll
        for (int ks = 0; ks < 4; ks++) {
            const int kk = ks * 8;
            unsigned a[2][4], bf[2][2];
            #pragma unroll
            for (int mi = 0; mi < 2; mi++) {
                const int m = m0 + mi * 16;
                a[mi][0] = __float_as_uint(As[stg][m + ln4    ][kk + lm4    ]);
                a[mi][1] = __float_as_uint(As[stg][m + ln4 + 8][kk + lm4    ]);
                a[mi][2] = __float_as_uint(As[stg][m + ln4    ][kk + lm4 + 4]);
                a[mi][3] = __float_as_uint(As[stg][m + ln4 + 8][kk + lm4 + 4]);
            }
            #pragma unroll
            for (int ni = 0; ni < 2; ni++) {
                const int n = n0 + ni * 8;
                bf[ni][0] = __float_as_uint(Ws[stg][kk + lm4    ][n + ln4]);
                bf[ni][1] = __float_as_uint(Ws[stg][kk + lm4 + 4][n + ln4]);
            }
            #pragma unroll
            for (int mi = 0; mi < 2; mi++)
                #pragma unroll
                for (int ni = 0; ni < 2; ni++)
                    mma_tf32(acc[mi][ni], a[mi], bf[ni]);
        }
        __syncthreads();   // all reads of stage kt done before it is refilled (kt+3)
    }
    #undef LOAD_STAGE

    #pragma unroll
    for (int mi = 0; mi < 2; mi++) {
        #pragma unroll
        for (int ni = 0; ni < 2; ni++) {
            int gr = bm + m0 + mi * 16 + ln4;
            int gc = bn + n0 + ni * 8 + lm4 * 2;
            *(float2*)(C + (size_t)gr * 256 + gc) =
                make_float2(acc[mi][ni][0], acc[mi][ni][1]);
            *(float2*)(C + (size_t)(gr + 8) * 256 + gc) =
                make_float2(acc[mi][ni][2], acc[mi][ni][3]);
        }
    }
}

// ---------------------------------------------------------------------------
// Scores: s[b,q,k] = sum_h tanh(qp[b,q,h] + kp[b,k,h]) * wv[h]
// block = (b, 16 q, 64 k); MUFU.TANH (measured floor); masked tiles exit.
// ---------------------------------------------------------------------------
__global__ __launch_bounds__(256) void scores_kernel(
    const float* __restrict__ wv, const int* __restrict__ valid_lens) {
    __shared__ float qp_s[16][68];
    __shared__ float kp_s[64][68];
    __shared__ float wv_s[HH];

    const int kt = blockIdx.x;
    const int qt = blockIdx.y;
    const int b  = blockIdx.z;
    if (kt * 64 >= valid_lens[b]) return;

    const int t  = threadIdx.x;
    const int kl = t % 64;
    const int qg = t / 64;

    if (t < HH) wv_s[t] = wv[t];

    const float* qp_base = g_qp + ((size_t)b * TQ + qt * 16) * HH;
    const float* kp_base = g_kp + ((size_t)b * TK + kt * 64) * HH;

    u64 acc[4] = {0ull, 0ull, 0ull, 0ull};

    for (int c = 0; c < 4; c++) {
        const int h0 = c * 64;
        __syncthreads();
        {
            int row = t / 16, col = (t % 16) * 4;
            *(float4*)&qp_s[row][col] =
                *(const float4*)(qp_base + (size_t)row * HH + h0 + col);
            #pragma unroll
            for (int j = 0; j < 4; j++) {
                int kr = row + j * 16;
                *(float4*)&kp_s[kr][col] =
                    *(const float4*)(kp_base + (size_t)kr * HH + h0 + col);
            }
        }
        __syncthreads();
        #pragma unroll
        for (int h4 = 0; h4 < 16; h4++) {
            ulonglong2 kv2 = *(const ulonglong2*)&kp_s[kl][h4 * 4];
            ulonglong2 wv2 = *(const ulonglong2*)&wv_s[h0 + h4 * 4];
            #pragma unroll
            for (int i = 0; i < 4; i++) {
                ulonglong2 qv2 = *(const ulonglong2*)&qp_s[qg * 4 + i][h4 * 4];
                float2 s0 = unpack2(fadd2(qv2.x, kv2.x));
                float2 s1 = unpack2(fadd2(qv2.y, kv2.y));
                u64 t0 = pack2(tanh_fast(s0.x), tanh_fast(s0.y));
                u64 t1 = pack2(tanh_fast(s1.x), tanh_fast(s1.y));
                acc[i] = ffma2(t0, wv2.x, acc[i]);
                acc[i] = ffma2(t1, wv2.y, acc[i]);
            }
        }
    }
    #pragma unroll
    for (int i = 0; i < 4; i++) {
        int q = qt * 16 + qg * 4 + i;
        g_attn[((size_t)b * TQ + q) * TK + kt * 64 + kl] = sum2(acc[i]);
    }
}

// ---------------------------------------------------------------------------
// Fused masked-softmax + AV, d-split for occupancy.
// grid = (qt 16, dseg 4, b 8), 128 threads. AV loop unrolled x2 for MLP.
// ---------------------------------------------------------------------------
__global__ __launch_bounds__(128) void softmax_av_kernel(
    const float* __restrict__ values, const int* __restrict__ valid_lens,
    float* __restrict__ out) {
    __shared__ float attn_s[8][512];   // 16 KB

    const int t  = threadIdx.x;
    const int qt = blockIdx.x;         // 0..15
    const int ds = blockIdx.y;         // 0..3  (64 d cols each)
    const int b  = blockIdx.z;
    const int vl = valid_lens[b];

    {
        const float4* src = (const float4*)(g_attn + ((size_t)b * TQ + qt * 8) * TK);
        float4* dst = (float4*)&attn_s[0][0];
        #pragma unroll
        for (int j = 0; j < 8; j++) dst[t + 128 * j] = src[t + 128 * j];
    }
    __syncthreads();

    {
        const int w    = t / 32;
        const int lane = t % 32;
        #pragma unroll
        for (int r = 0; r < 2; r++) {
            float* row = attn_s[w * 2 + r];
            float v[16];
            float mx = -INFINITY;
            #pragma unroll
            for (int j = 0; j < 16; j++) {
                int kk = lane + 32 * j;
                v[j] = row[kk];
                if (kk < vl) mx = fmaxf(mx, v[j]);
            }
            #pragma unroll
            for (int o = 16; o > 0; o >>= 1)
                mx = fmaxf(mx, __shfl_xor_sync(0xffffffff, mx, o));
            float sum = 0.f;
            #pragma unroll
            for (int j = 0; j < 16; j++) {
                int kk = lane + 32 * j;
                v[j] = (kk < vl) ? __expf(v[j] - mx) : 0.f;
                sum += v[j];
            }
            #pragma unroll
            for (int o = 16; o > 0; o >>= 1)
                sum += __shfl_xor_sync(0xffffffff, sum, o);
            float inv = 1.0f / sum;
            #pragma unroll
            for (int j = 0; j < 16; j++)
                row[lane + 32 * j] = v[j] * inv;
        }
    }
    __syncthreads();

    const int tq = t >> 4;
    const int dl = ds * 64 + (t & 15) * 4;
    const float* vbase = values + (size_t)b * TK * DD;
    const float* arow  = attn_s[tq];

    u64 acc[2] = {0ull, 0ull};
    const int k4max = (vl + 3) >> 2;   // attn beyond vl is exactly 0

    #pragma unroll 2
    for (int k4 = 0; k4 < k4max; k4++) {
        float4 a = *(const float4*)&arow[k4 * 4];
        float av[4] = {a.x, a.y, a.z, a.w};
        #pragma unroll
        for (int kk = 0; kk < 4; kk++) {
            ulonglong2 v2 = *(const ulonglong2*)(vbase + (size_t)(k4 * 4 + kk) * DD + dl);
            u64 ad = pack2(av[kk], av[kk]);
            acc[0] = ffma2(ad, v2.x, acc[0]);
            acc[1] = ffma2(ad, v2.y, acc[1]);
        }
    }

    {
        int q = qt * 8 + tq;
        float2 lo = unpack2(acc[0]), hi = unpack2(acc[1]);
        *(float4*)(out + ((size_t)b * TQ + q) * DD + dl) =
            make_float4(lo.x, lo.y, hi.x, hi.y);
    }
}

// ---------------------------------------------------------------------------
// Inputs (metadata order): queries, keys, values, valid_lens, Wq, Wk, wv
// ---------------------------------------------------------------------------
extern "C" void kernel_launch(void* const* d_in, const int* in_sizes, int n_in,
                              void* d_out, int out_size) {
    const float* queries    = (const float*)d_in[0];
    const float* keys       = (const float*)d_in[1];
    const float* values     = (const float*)d_in[2];
    const int*   valid_lens = (const int*)d_in[3];
    const float* Wq         = (const float*)d_in[4];
    const float* Wk         = (const float*)d_in[5];
    const float* wv         = (const float*)d_in[6];
    float*       out        = (float*)d_out;

    // projections (TF32 tensor cores, no-cvt, 3-stage pipe)
    proj_kernel<<<dim3(4, 80), 256>>>(queries, keys, Wq, Wk, valid_lens);
    // scores (MUFU tanh, masked k-tiles skipped)
    scores_kernel<<<dim3(8, 8, 8), 256>>>(wv, valid_lens);
    // fused masked softmax + AV, d-split
    softmax_av_kernel<<<dim3(16, 4, 8), 128>>>(values, valid_lens, out);
}

// round 14
// speedup vs baseline: 1.1033x; 1.1033x over previous
#include <cuda_runtime.h>
#include <math.h>

#define B  8
#define TQ 128
#define TK 512
#define DD 256
#define HH 256

// Scratch (no allocations allowed)
__device__ float g_qp[B * TQ * HH];     // 1 MB
__device__ float g_kp[B * TK * HH];     // 4 MB (rows >= valid_lens[b] stay garbage — masked later)
__device__ float g_attn[B * TQ * TK];   // 2 MB (raw scores; masked cols garbage — masked later)

typedef unsigned long long u64;

__device__ __forceinline__ float tanh_fast(float x) {
    float y;
    asm("tanh.approx.f32 %0, %1;" : "=f"(y) : "f"(x));
    return y;
}
__device__ __forceinline__ u64 ffma2(u64 a, u64 b, u64 c) {
    u64 d;
    asm("fma.rn.f32x2 %0, %1, %2, %3;" : "=l"(d) : "l"(a), "l"(b), "l"(c));
    return d;
}
__device__ __forceinline__ u64 fadd2(u64 a, u64 b) {
    u64 d;
    asm("add.rn.f32x2 %0, %1, %2;" : "=l"(d) : "l"(a), "l"(b));
    return d;
}
__device__ __forceinline__ u64 pack2(float lo, float hi) {
    u64 r;
    asm("mov.b64 %0, {%1, %2};" : "=l"(r) : "f"(lo), "f"(hi));
    return r;
}
__device__ __forceinline__ float2 unpack2(u64 v) {
    float lo, hi;
    asm("mov.b64 {%0, %1}, %2;" : "=f"(lo), "=f"(hi) : "l"(v));
    return make_float2(lo, hi);
}
__device__ __forceinline__ float sum2(u64 v) {
    float2 f = unpack2(v);
    return f.x + f.y;
}

__device__ __forceinline__ unsigned smem_u32(const void* p) {
    return (unsigned)__cvta_generic_to_shared(p);
}
__device__ __forceinline__ void cp_async16(unsigned dst, const void* src) {
    asm volatile("cp.async.cg.shared.global [%0], [%1], 16;\n"
                 :: "r"(dst), "l"(src));
}
__device__ __forceinline__ void cp_commit() {
    asm volatile("cp.async.commit_group;\n");
}
template <int N>
__device__ __forceinline__ void cp_wait() {
    asm volatile("cp.async.wait_group %0;\n" :: "n"(N));
}

// D = A(16x8, row) * B(8x8, col) + D, tf32 in / f32 accum.
// Operands are raw f32 bits: HW reads the top 19 bits (RZ truncation to tf32),
// saving all cvt.rna.tf32 instructions at ~2^-10 operand error.
__device__ __forceinline__ void mma_tf32(float* c, const unsigned* a, const unsigned* b) {
    asm("mma.sync.aligned.m16n8k8.row.col.f32.tf32.tf32.f32 "
        "{%0,%1,%2,%3}, {%4,%5,%6,%7}, {%8,%9}, {%0,%1,%2,%3};"
        : "+f"(c[0]), "+f"(c[1]), "+f"(c[2]), "+f"(c[3])
        : "r"(a[0]), "r"(a[1]), "r"(a[2]), "r"(a[3]), "r"(b[0]), "r"(b[1]));
}

// ---------------------------------------------------------------------------
// Combined projection GEMM on tensor cores (TF32 mma.sync, no-cvt fast path).
// 64m x 32n block tile, 128 threads (4 warps: 2m x 2n, warp tile 32m x 16n).
// BK=32, cp.async double buffer (2-stage — 3-stage measured slower).
// 640 blocks: small 4-warp barrier domains, 2x blocks/SM for cross-block
// overlap (mechanism validated R4/R6). Masked 64-row k blocks exit early.
// Bank-conflict-free fragment reads: A pad 36 ((4*ln4+lm4)%32 distinct),
// B pad 40 ((8*lm4+ln4)%32 distinct).
// ---------------------------------------------------------------------------
__global__ __launch_bounds__(128) void proj_kernel(
    const float* __restrict__ q, const float* __restrict__ k,
    const float* __restrict__ Wq, const float* __restrict__ Wk,
    const int* __restrict__ valid_lens) {
    __shared__ float As[2][64][36];   // [buf][m][k]
    __shared__ float Ws[2][32][40];   // [buf][k][n]

    const int by = blockIdx.y;
    const float* A; const float* W; float* C; int bm;
    if (by < 16) {
        A = q; W = Wq; C = g_qp; bm = by * 64;
    } else {
        bm = (by - 16) * 64;             // k row in [0, 4096)
        int b = bm >> 9;
        int local = bm & 511;
        if (local >= valid_lens[b]) return;   // fully-masked k rows
        A = k; W = Wk; C = g_kp;
    }

    const int t    = threadIdx.x;
    const int bn   = blockIdx.x * 32;
    const int lane = t & 31;
    const int wid  = t >> 5;             // 0..3
    const int m0   = (wid & 1) * 32;
    const int n0   = (wid >> 1) * 16;
    const int ln4  = lane >> 2;          // 0..7
    const int lm4  = lane & 3;           // 0..3

    const float* Abase = A + (size_t)bm * 256;
    const float* Wbase = W + bn;

    unsigned sA[2], sB[2];
    sA[0] = smem_u32(&As[0][0][0]); sA[1] = smem_u32(&As[1][0][0]);
    sB[0] = smem_u32(&Ws[0][0][0]); sB[1] = smem_u32(&Ws[1][0][0]);

    // A tile 64x32 = 512 float4 (4/thread); B tile 32x32 = 256 float4 (2/thread)
    #define LOAD_STAGE(buf, kt)                                                   \
        do {                                                                      \
            int _k0 = (kt) * 32;                                                  \
            _Pragma("unroll")                                                     \
            for (int j = 0; j < 4; j++) {                                         \
                int u = t + 128 * j;                                              \
                int r = u >> 3, c4 = (u & 7) * 4;                                 \
                cp_async16(sA[buf] + (r * 36 + c4) * 4,                           \
                           Abase + (size_t)r * 256 + _k0 + c4);                   \
            }                                                                     \
            _Pragma("unroll")                                                     \
            for (int j = 0; j < 2; j++) {                                         \
                int u = t + 128 * j;                                              \
                int r = u >> 3, c4 = (u & 7) * 4;                                 \
                cp_async16(sB[buf] + (r * 40 + c4) * 4,                           \
                           Wbase + (size_t)(_k0 + r) * 256 + c4);                 \
            }                                                                     \
            cp_commit();                                                          \
        } while (0)

    float acc[2][2][4] = {};   // [mi][ni][4]

    LOAD_STAGE(0, 0);

    #pragma unroll 1
    for (int kt = 0; kt < 8; kt++) {
        const int buf = kt & 1;
        if (kt + 1 < 8) {
            LOAD_STAGE(buf ^ 1, kt + 1);
            cp_wait<1>();
        } else {
            cp_wait<0>();
        }
        __syncthreads();

        #pragma unroll
        for (int ks = 0; ks < 4; ks++) {
            const int kk = ks * 8;
            unsigned a[2][4], bf[2][2];
            #pragma unroll
            for (int mi = 0; mi < 2; mi++) {
                const int m = m0 + mi * 16;
                a[mi][0] = __float_as_uint(As[buf][m + ln4    ][kk + lm4    ]);
                a[mi][1] = __float_as_uint(As[buf][m + ln4 + 8][kk + lm4    ]);
                a[mi][2] = __float_as_uint(As[buf][m + ln4    ][kk + lm4 + 4]);
                a[mi][3] = __float_as_uint(As[buf][m + ln4 + 8][kk + lm4 + 4]);
            }
            #pragma unroll
            for (int ni = 0; ni < 2; ni++) {
                const int n = n0 + ni * 8;
                bf[ni][0] = __float_as_uint(Ws[buf][kk + lm4    ][n + ln4]);
                bf[ni][1] = __float_as_uint(Ws[buf][kk + lm4 + 4][n + ln4]);
            }
            #pragma unroll
            for (int mi = 0; mi < 2; mi++)
                #pragma unroll
                for (int ni = 0; ni < 2; ni++)
                    mma_tf32(acc[mi][ni], a[mi], bf[ni]);
        }
        __syncthreads();
    }
    #undef LOAD_STAGE

    #pragma unroll
    for (int mi = 0; mi < 2; mi++) {
        #pragma unroll
        for (int ni = 0; ni < 2; ni++) {
            int gr = bm + m0 + mi * 16 + ln4;
            int gc = bn + n0 + ni * 8 + lm4 * 2;
            *(float2*)(C + (size_t)gr * 256 + gc) =
                make_float2(acc[mi][ni][0], acc[mi][ni][1]);
            *(float2*)(C + (size_t)(gr + 8) * 256 + gc) =
                make_float2(acc[mi][ni][2], acc[mi][ni][3]);
        }
    }
}

// ---------------------------------------------------------------------------
// Scores: s[b,q,k] = sum_h tanh(qp[b,q,h] + kp[b,k,h]) * wv[h]
// block = (b, 16 q, 64 k); MUFU.TANH (measured floor); masked tiles exit.
// (round-12 exact)
// ---------------------------------------------------------------------------
__global__ __launch_bounds__(256) void scores_kernel(
    const float* __restrict__ wv, const int* __restrict__ valid_lens) {
    __shared__ float qp_s[16][68];
    __shared__ float kp_s[64][68];
    __shared__ float wv_s[HH];

    const int kt = blockIdx.x;
    const int qt = blockIdx.y;
    const int b  = blockIdx.z;
    if (kt * 64 >= valid_lens[b]) return;

    const int t  = threadIdx.x;
    const int kl = t % 64;
    const int qg = t / 64;

    if (t < HH) wv_s[t] = wv[t];

    const float* qp_base = g_qp + ((size_t)b * TQ + qt * 16) * HH;
    const float* kp_base = g_kp + ((size_t)b * TK + kt * 64) * HH;

    u64 acc[4] = {0ull, 0ull, 0ull, 0ull};

    for (int c = 0; c < 4; c++) {
        const int h0 = c * 64;
        __syncthreads();
        {
            int row = t / 16, col = (t % 16) * 4;
            *(float4*)&qp_s[row][col] =
                *(const float4*)(qp_base + (size_t)row * HH + h0 + col);
            #pragma unroll
            for (int j = 0; j < 4; j++) {
                int kr = row + j * 16;
                *(float4*)&kp_s[kr][col] =
                    *(const float4*)(kp_base + (size_t)kr * HH + h0 + col);
            }
        }
        __syncthreads();
        #pragma unroll
        for (int h4 = 0; h4 < 16; h4++) {
            ulonglong2 kv2 = *(const ulonglong2*)&kp_s[kl][h4 * 4];
            ulonglong2 wv2 = *(const ulonglong2*)&wv_s[h0 + h4 * 4];
            #pragma unroll
            for (int i = 0; i < 4; i++) {
                ulonglong2 qv2 = *(const ulonglong2*)&qp_s[qg * 4 + i][h4 * 4];
                float2 s0 = unpack2(fadd2(qv2.x, kv2.x));
                float2 s1 = unpack2(fadd2(qv2.y, kv2.y));
                u64 t0 = pack2(tanh_fast(s0.x), tanh_fast(s0.y));
                u64 t1 = pack2(tanh_fast(s1.x), tanh_fast(s1.y));
                acc[i] = ffma2(t0, wv2.x, acc[i]);
                acc[i] = ffma2(t1, wv2.y, acc[i]);
            }
        }
    }
    #pragma unroll
    for (int i = 0; i < 4; i++) {
        int q = qt * 16 + qg * 4 + i;
        g_attn[((size_t)b * TQ + q) * TK + kt * 64 + kl] = sum2(acc[i]);
    }
}

// ---------------------------------------------------------------------------
// Fused masked-softmax + AV, d-split for occupancy. (round-12 exact, no unroll)
// grid = (qt 16, dseg 4, b 8), 128 threads.
// ---------------------------------------------------------------------------
__global__ __launch_bounds__(128) void softmax_av_kernel(
    const float* __restrict__ values, const int* __restrict__ valid_lens,
    float* __restrict__ out) {
    __shared__ float attn_s[8][512];   // 16 KB

    const int t  = threadIdx.x;
    const int qt = blockIdx.x;         // 0..15
    const int ds = blockIdx.y;         // 0..3  (64 d cols each)
    const int b  = blockIdx.z;
    const int vl = valid_lens[b];

    {
        const float4* src = (const float4*)(g_attn + ((size_t)b * TQ + qt * 8) * TK);
        float4* dst = (float4*)&attn_s[0][0];
        #pragma unroll
        for (int j = 0; j < 8; j++) dst[t + 128 * j] = src[t + 128 * j];
    }
    __syncthreads();

    {
        const int w    = t / 32;
        const int lane = t % 32;
        #pragma unroll
        for (int r = 0; r < 2; r++) {
            float* row = attn_s[w * 2 + r];
            float v[16];
            float mx = -INFINITY;
            #pragma unroll
            for (int j = 0; j < 16; j++) {
                int kk = lane + 32 * j;
                v[j] = row[kk];
                if (kk < vl) mx = fmaxf(mx, v[j]);
            }
            #pragma unroll
            for (int o = 16; o > 0; o >>= 1)
                mx = fmaxf(mx, __shfl_xor_sync(0xffffffff, mx, o));
            float sum = 0.f;
            #pragma unroll
            for (int j = 0; j < 16; j++) {
                int kk = lane + 32 * j;
                v[j] = (kk < vl) ? __expf(v[j] - mx) : 0.f;
                sum += v[j];
            }
            #pragma unroll
            for (int o = 16; o > 0; o >>= 1)
                sum += __shfl_xor_sync(0xffffffff, sum, o);
            float inv = 1.0f / sum;
            #pragma unroll
            for (int j = 0; j < 16; j++)
                row[lane + 32 * j] = v[j] * inv;
        }
    }
    __syncthreads();

    const int tq = t >> 4;
    const int dl = ds * 64 + (t & 15) * 4;
    const float* vbase = values + (size_t)b * TK * DD;
    const float* arow  = attn_s[tq];

    u64 acc[2] = {0ull, 0ull};
    const int k4max = (vl + 3) >> 2;   // attn beyond vl is exactly 0

    for (int k4 = 0; k4 < k4max; k4++) {
        float4 a = *(const float4*)&arow[k4 * 4];
        float av[4] = {a.x, a.y, a.z, a.w};
        #pragma unroll
        for (int kk = 0; kk < 4; kk++) {
            ulonglong2 v2 = *(const ulonglong2*)(vbase + (size_t)(k4 * 4 + kk) * DD + dl);
            u64 ad = pack2(av[kk], av[kk]);
            acc[0] = ffma2(ad, v2.x, acc[0]);
            acc[1] = ffma2(ad, v2.y, acc[1]);
        }
    }

    {
        int q = qt * 8 + tq;
        float2 lo = unpack2(acc[0]), hi = unpack2(acc[1]);
        *(float4*)(out + ((size_t)b * TQ + q) * DD + dl) =
            make_float4(lo.x, lo.y, hi.x, hi.y);
    }
}

// ---------------------------------------------------------------------------
// Inputs (metadata order): queries, keys, values, valid_lens, Wq, Wk, wv
// ---------------------------------------------------------------------------
extern "C" void kernel_launch(void* const* d_in, const int* in_sizes, int n_in,
                              void* d_out, int out_size) {
    const float* queries    = (const float*)d_in[0];
    const float* keys       = (const float*)d_in[1];
    const float* values     = (const float*)d_in[2];
    const int*   valid_lens = (const int*)d_in[3];
    const float* Wq         = (const float*)d_in[4];
    const float* Wk         = (const float*)d_in[5];
    const float* wv         = (const float*)d_in[6];
    float*       out        = (float*)d_out;

    // projections (TF32, no-cvt, 640 small blocks): 16 q + 64 k row-blocks
    proj_kernel<<<dim3(8, 80), 128>>>(queries, keys, Wq, Wk, valid_lens);
    // scores (MUFU tanh, masked k-tiles skipped)
    scores_kernel<<<dim3(8, 8, 8), 256>>>(wv, valid_lens);
    // fused masked softmax + AV, d-split
    softmax_av_kernel<<<dim3(16, 4, 8), 128>>>(values, valid_lens, out);
}

// round 15
// speedup vs baseline: 1.1249x; 1.0195x over previous
#include <cuda_runtime.h>
#include <math.h>

#define B  8
#define TQ 128
#define TK 512
#define DD 256
#define HH 256

// Scratch (no allocations allowed)
__device__ float g_qp[B * TQ * HH];     // 1 MB
__device__ float g_kp[B * TK * HH];     // 4 MB (rows >= valid_lens[b] stay garbage — masked later)
__device__ float g_attn[B * TQ * TK];   // 2 MB (raw scores; masked cols garbage — masked later)

typedef unsigned long long u64;

__device__ __forceinline__ float tanh_fast(float x) {
    float y;
    asm("tanh.approx.f32 %0, %1;" : "=f"(y) : "f"(x));
    return y;
}
__device__ __forceinline__ u64 ffma2(u64 a, u64 b, u64 c) {
    u64 d;
    asm("fma.rn.f32x2 %0, %1, %2, %3;" : "=l"(d) : "l"(a), "l"(b), "l"(c));
    return d;
}
__device__ __forceinline__ u64 fadd2(u64 a, u64 b) {
    u64 d;
    asm("add.rn.f32x2 %0, %1, %2;" : "=l"(d) : "l"(a), "l"(b));
    return d;
}
__device__ __forceinline__ u64 pack2(float lo, float hi) {
    u64 r;
    asm("mov.b64 %0, {%1, %2};" : "=l"(r) : "f"(lo), "f"(hi));
    return r;
}
__device__ __forceinline__ float2 unpack2(u64 v) {
    float lo, hi;
    asm("mov.b64 {%0, %1}, %2;" : "=f"(lo), "=f"(hi) : "l"(v));
    return make_float2(lo, hi);
}
__device__ __forceinline__ float sum2(u64 v) {
    float2 f = unpack2(v);
    return f.x + f.y;
}

__device__ __forceinline__ unsigned smem_u32(const void* p) {
    return (unsigned)__cvta_generic_to_shared(p);
}
__device__ __forceinline__ void cp_async16(unsigned dst, const void* src) {
    asm volatile("cp.async.cg.shared.global [%0], [%1], 16;\n"
                 :: "r"(dst), "l"(src));
}
__device__ __forceinline__ void cp_commit() {
    asm volatile("cp.async.commit_group;\n");
}
template <int N>
__device__ __forceinline__ void cp_wait() {
    asm volatile("cp.async.wait_group %0;\n" :: "n"(N));
}

// D = A(16x8, row) * B(8x8, col) + D, tf32 in / f32 accum.
// Operands are raw f32 bits: HW reads the top 19 bits (RZ truncation to tf32),
// saving all cvt.rna.tf32 instructions at ~2^-10 operand error.
__device__ __forceinline__ void mma_tf32(float* c, const unsigned* a, const unsigned* b) {
    asm("mma.sync.aligned.m16n8k8.row.col.f32.tf32.tf32.f32 "
        "{%0,%1,%2,%3}, {%4,%5,%6,%7}, {%8,%9}, {%0,%1,%2,%3};"
        : "+f"(c[0]), "+f"(c[1]), "+f"(c[2]), "+f"(c[3])
        : "r"(a[0]), "r"(a[1]), "r"(a[2]), "r"(a[3]), "r"(b[0]), "r"(b[1]));
}

// ---------------------------------------------------------------------------
// Combined projection GEMM on tensor cores (TF32 mma.sync, no-cvt fast path).
// 32m x 32n block tile, 128 threads (4 warps: 2m x 2n, warp tile 16m x 16n).
// BK=32, cp.async double buffer. grid = (8 n-tiles, 160 row-blocks) = 1280
// blocks — continuing the measured-winning direction (R4/R6/R14): max block
// count for cross-block latency overlap. Masked 32-row k blocks exit early.
// Bank-conflict-free fragment reads: A pad 36 ((4*ln4+lm4)%32 distinct),
// B pad 40 ((8*lm4+ln4)%32 distinct).
// ---------------------------------------------------------------------------
__global__ __launch_bounds__(128) void proj_kernel(
    const float* __restrict__ q, const float* __restrict__ k,
    const float* __restrict__ Wq, const float* __restrict__ Wk,
    const int* __restrict__ valid_lens) {
    __shared__ float As[2][32][36];   // [buf][m][k]
    __shared__ float Ws[2][32][40];   // [buf][k][n]

    const int by = blockIdx.y;
    const float* A; const float* W; float* C; int bm;
    if (by < 32) {
        A = q; W = Wq; C = g_qp; bm = by * 32;
    } else {
        bm = (by - 32) * 32;             // k row in [0, 4096)
        int b = bm >> 9;
        int local = bm & 511;
        if (local >= valid_lens[b]) return;   // fully-masked k rows
        A = k; W = Wk; C = g_kp;
    }

    const int t    = threadIdx.x;
    const int bn   = blockIdx.x * 32;
    const int lane = t & 31;
    const int wid  = t >> 5;             // 0..3
    const int m0   = (wid & 1) * 16;
    const int n0   = (wid >> 1) * 16;
    const int ln4  = lane >> 2;          // 0..7
    const int lm4  = lane & 3;           // 0..3

    const float* Abase = A + (size_t)bm * 256;
    const float* Wbase = W + bn;

    unsigned sA[2], sB[2];
    sA[0] = smem_u32(&As[0][0][0]); sA[1] = smem_u32(&As[1][0][0]);
    sB[0] = smem_u32(&Ws[0][0][0]); sB[1] = smem_u32(&Ws[1][0][0]);

    // A tile 32x32 = 256 float4 (2/thread); B tile 32x32 = 256 float4 (2/thread)
    #define LOAD_STAGE(buf, kt)                                                   \
        do {                                                                      \
            int _k0 = (kt) * 32;                                                  \
            _Pragma("unroll")                                                     \
            for (int j = 0; j < 2; j++) {                                         \
                int u = t + 128 * j;                                              \
                int r = u >> 3, c4 = (u & 7) * 4;                                 \
                cp_async16(sA[buf] + (r * 36 + c4) * 4,                           \
                           Abase + (size_t)r * 256 + _k0 + c4);                   \
                cp_async16(sB[buf] + (r * 40 + c4) * 4,                           \
                           Wbase + (size_t)(_k0 + r) * 256 + c4);                 \
            }                                                                     \
            cp_commit();                                                          \
        } while (0)

    float acc[2][4] = {};   // [ni][4]

    LOAD_STAGE(0, 0);

    #pragma unroll 1
    for (int kt = 0; kt < 8; kt++) {
        const int buf = kt & 1;
        if (kt + 1 < 8) {
            LOAD_STAGE(buf ^ 1, kt + 1);
            cp_wait<1>();
        } else {
            cp_wait<0>();
        }
        __syncthreads();

        #pragma unroll
        for (int ks = 0; ks < 4; ks++) {
            const int kk = ks * 8;
            unsigned a[4], bf[2][2];
            a[0] = __float_as_uint(As[buf][m0 + ln4    ][kk + lm4    ]);
            a[1] = __float_as_uint(As[buf][m0 + ln4 + 8][kk + lm4    ]);
            a[2] = __float_as_uint(As[buf][m0 + ln4    ][kk + lm4 + 4]);
            a[3] = __float_as_uint(As[buf][m0 + ln4 + 8][kk + lm4 + 4]);
            #pragma unroll
            for (int ni = 0; ni < 2; ni++) {
                const int n = n0 + ni * 8;
                bf[ni][0] = __float_as_uint(Ws[buf][kk + lm4    ][n + ln4]);
                bf[ni][1] = __float_as_uint(Ws[buf][kk + lm4 + 4][n + ln4]);
            }
            #pragma unroll
            for (int ni = 0; ni < 2; ni++)
                mma_tf32(acc[ni], a, bf[ni]);
        }
        __syncthreads();
    }
    #undef LOAD_STAGE

    #pragma unroll
    for (int ni = 0; ni < 2; ni++) {
        int gr = bm + m0 + ln4;
        int gc = bn + n0 + ni * 8 + lm4 * 2;
        *(float2*)(C + (size_t)gr * 256 + gc) =
            make_float2(acc[ni][0], acc[ni][1]);
        *(float2*)(C + (size_t)(gr + 8) * 256 + gc) =
            make_float2(acc[ni][2], acc[ni][3]);
    }
}

// ---------------------------------------------------------------------------
// Scores: s[b,q,k] = sum_h tanh(qp[b,q,h] + kp[b,k,h]) * wv[h]
// block = (b, 16 q, 64 k); MUFU.TANH (measured floor); masked tiles exit.
// (round-12 exact)
// ---------------------------------------------------------------------------
__global__ __launch_bounds__(256) void scores_kernel(
    const float* __restrict__ wv, const int* __restrict__ valid_lens) {
    __shared__ float qp_s[16][68];
    __shared__ float kp_s[64][68];
    __shared__ float wv_s[HH];

    const int kt = blockIdx.x;
    const int qt = blockIdx.y;
    const int b  = blockIdx.z;
    if (kt * 64 >= valid_lens[b]) return;

    const int t  = threadIdx.x;
    const int kl = t % 64;
    const int qg = t / 64;

    if (t < HH) wv_s[t] = wv[t];

    const float* qp_base = g_qp + ((size_t)b * TQ + qt * 16) * HH;
    const float* kp_base = g_kp + ((size_t)b * TK + kt * 64) * HH;

    u64 acc[4] = {0ull, 0ull, 0ull, 0ull};

    for (int c = 0; c < 4; c++) {
        const int h0 = c * 64;
        __syncthreads();
        {
            int row = t / 16, col = (t % 16) * 4;
            *(float4*)&qp_s[row][col] =
                *(const float4*)(qp_base + (size_t)row * HH + h0 + col);
            #pragma unroll
            for (int j = 0; j < 4; j++) {
                int kr = row + j * 16;
                *(float4*)&kp_s[kr][col] =
                    *(const float4*)(kp_base + (size_t)kr * HH + h0 + col);
            }
        }
        __syncthreads();
        #pragma unroll
        for (int h4 = 0; h4 < 16; h4++) {
            ulonglong2 kv2 = *(const ulonglong2*)&kp_s[kl][h4 * 4];
            ulonglong2 wv2 = *(const ulonglong2*)&wv_s[h0 + h4 * 4];
            #pragma unroll
            for (int i = 0; i < 4; i++) {
                ulonglong2 qv2 = *(const ulonglong2*)&qp_s[qg * 4 + i][h4 * 4];
                float2 s0 = unpack2(fadd2(qv2.x, kv2.x));
                float2 s1 = unpack2(fadd2(qv2.y, kv2.y));
                u64 t0 = pack2(tanh_fast(s0.x), tanh_fast(s0.y));
                u64 t1 = pack2(tanh_fast(s1.x), tanh_fast(s1.y));
                acc[i] = ffma2(t0, wv2.x, acc[i]);
                acc[i] = ffma2(t1, wv2.y, acc[i]);
            }
        }
    }
    #pragma unroll
    for (int i = 0; i < 4; i++) {
        int q = qt * 16 + qg * 4 + i;
        g_attn[((size_t)b * TQ + q) * TK + kt * 64 + kl] = sum2(acc[i]);
    }
}

// ---------------------------------------------------------------------------
// Fused masked-softmax + AV, d-split for occupancy. (round-12 exact)
// grid = (qt 16, dseg 4, b 8), 128 threads.
// ---------------------------------------------------------------------------
__global__ __launch_bounds__(128) void softmax_av_kernel(
    const float* __restrict__ values, const int* __restrict__ valid_lens,
    float* __restrict__ out) {
    __shared__ float attn_s[8][512];   // 16 KB

    const int t  = threadIdx.x;
    const int qt = blockIdx.x;         // 0..15
    const int ds = blockIdx.y;         // 0..3  (64 d cols each)
    const int b  = blockIdx.z;
    const int vl = valid_lens[b];

    {
        const float4* src = (const float4*)(g_attn + ((size_t)b * TQ + qt * 8) * TK);
        float4* dst = (float4*)&attn_s[0][0];
        #pragma unroll
        for (int j = 0; j < 8; j++) dst[t + 128 * j] = src[t + 128 * j];
    }
    __syncthreads();

    {
        const int w    = t / 32;
        const int lane = t % 32;
        #pragma unroll
        for (int r = 0; r < 2; r++) {
            float* row = attn_s[w * 2 + r];
            float v[16];
            float mx = -INFINITY;
            #pragma unroll
            for (int j = 0; j < 16; j++) {
                int kk = lane + 32 * j;
                v[j] = row[kk];
                if (kk < vl) mx = fmaxf(mx, v[j]);
            }
            #pragma unroll
            for (int o = 16; o > 0; o >>= 1)
                mx = fmaxf(mx, __shfl_xor_sync(0xffffffff, mx, o));
            float sum = 0.f;
            #pragma unroll
            for (int j = 0; j < 16; j++) {
                int kk = lane + 32 * j;
                v[j] = (kk < vl) ? __expf(v[j] - mx) : 0.f;
                sum += v[j];
            }
            #pragma unroll
            for (int o = 16; o > 0; o >>= 1)
                sum += __shfl_xor_sync(0xffffffff, sum, o);
            float inv = 1.0f / sum;
            #pragma unroll
            for (int j = 0; j < 16; j++)
                row[lane + 32 * j] = v[j] * inv;
        }
    }
    __syncthreads();

    const int tq = t >> 4;
    const int dl = ds * 64 + (t & 15) * 4;
    const float* vbase = values + (size_t)b * TK * DD;
    const float* arow  = attn_s[tq];

    u64 acc[2] = {0ull, 0ull};
    const int k4max = (vl + 3) >> 2;   // attn beyond vl is exactly 0

    for (int k4 = 0; k4 < k4max; k4++) {
        float4 a = *(const float4*)&arow[k4 * 4];
        float av[4] = {a.x, a.y, a.z, a.w};
        #pragma unroll
        for (int kk = 0; kk < 4; kk++) {
            ulonglong2 v2 = *(const ulonglong2*)(vbase + (size_t)(k4 * 4 + kk) * DD + dl);
            u64 ad = pack2(av[kk], av[kk]);
            acc[0] = ffma2(ad, v2.x, acc[0]);
            acc[1] = ffma2(ad, v2.y, acc[1]);
        }
    }

    {
        int q = qt * 8 + tq;
        float2 lo = unpack2(acc[0]), hi = unpack2(acc[1]);
        *(float4*)(out + ((size_t)b * TQ + q) * DD + dl) =
            make_float4(lo.x, lo.y, hi.x, hi.y);
    }
}

// ---------------------------------------------------------------------------
// Inputs (metadata order): queries, keys, values, valid_lens, Wq, Wk, wv
// ---------------------------------------------------------------------------
extern "C" void kernel_launch(void* const* d_in, const int* in_sizes, int n_in,
                              void* d_out, int out_size) {
    const float* queries    = (const float*)d_in[0];
    const float* keys       = (const float*)d_in[1];
    const float* values     = (const float*)d_in[2];
    const int*   valid_lens = (const int*)d_in[3];
    const float* Wq         = (const float*)d_in[4];
    const float* Wk         = (const float*)d_in[5];
    const float* wv         = (const float*)d_in[6];
    float*       out        = (float*)d_out;

    // projections (TF32, no-cvt, 1280 small blocks): 32 q + 128 k row-blocks
    proj_kernel<<<dim3(8, 160), 128>>>(queries, keys, Wq, Wk, valid_lens);
    // scores (MUFU tanh, masked k-tiles skipped)
    scores_kernel<<<dim3(8, 8, 8), 256>>>(wv, valid_lens);
    // fused masked softmax + AV, d-split
    softmax_av_kernel<<<dim3(16, 4, 8), 128>>>(values, valid_lens, out);
}